// round 2
// baseline (speedup 1.0000x reference)
#include <cuda_runtime.h>
#include <math.h>

// Problem constants
#define BB   16
#define CC   512
#define ICN  256
#define HH   64
#define NN   4096          // H*W
#define SS   110           // SPP pyramid total (1+9+36+64)
#define SPAD 128

// ---------------- scratch (device globals; no allocation allowed) ----------
__device__ float g_tg[(long long)BB * CC * NN];      // fused theta/g conv out [B,512,N] (rows 0..255 theta, 256..511 g)
__device__ float g_spp[BB * CC * SS];                // SPP of above: [B,512,S]
__device__ float g_kkT[BB * CC * SPAD];              // kk transposed: [B, c(512), s(pad 128)]
__device__ float g_v[BB * SS * CC];                  // v: [B, s, c]  (W_mask @ g_spp), later scaled by 1/sumexp
__device__ float g_logits[(long long)BB * SPAD * NN];// logits S-major: [B, s(pad 128), n] ; softmax -> exp values
__device__ float g_wT[CC * CC];                      // packed [k(c_in), m] m<256: theta row, else g row
__device__ float g_wmT[ICN * CC];                    // w_mask transposed: [ic, c]
__device__ float g_invsum[BB * SS];

// ---------------- weight pack -------------------------------------------
__global__ void pack_kernel(const float* __restrict__ wth, const float* __restrict__ wg,
                            const float* __restrict__ wmask) {
    int idx = blockIdx.x * blockDim.x + threadIdx.x;
    if (idx < CC * CC) {
        int k = idx / CC, m = idx % CC;      // g_wT[k*CC + m] = W_tg[m, k]
        g_wT[idx] = (m < ICN) ? wth[m * CC + k] : wg[(m - ICN) * CC + k];
    }
    if (idx < ICN * CC) {
        int ic = idx / CC, c = idx % CC;     // g_wmT[ic*CC + c] = w_mask[c, ic]
        g_wmT[idx] = wmask[c * ICN + ic];
    }
}

// ---------------- tiled SGEMM: C[m,n] (+= Cadd) = sum_k A[k*lda+m]*B[k*ldb+n]
#define BM 128
#define BN 128
#define BK 8

template <int ADD>
__global__ void __launch_bounds__(256)
sgemm_k(const float* __restrict__ A, const float* __restrict__ B,
        const float* __restrict__ Cadd, float* __restrict__ C,
        int M, int N, int K, int lda, int ldb, int ldc,
        long long sA, long long sB, long long sAdd, long long sC) {
    __shared__ float As[BK][BM];
    __shared__ float Bs[BK][BN];

    int b = blockIdx.z;
    A += b * sA;
    B += b * sB;
    C += b * sC;
    if (ADD) Cadd += b * sAdd;

    int bm = blockIdx.y * BM;
    int bn = blockIdx.x * BN;
    int tid = threadIdx.x;
    int lr = tid >> 5;            // 0..7 : k-row of the tile
    int lc = (tid & 31) * 4;      // 0..124: col (float4)
    int ty = tid >> 4;            // 0..15 -> rows ty*8..ty*8+7
    int tx = tid & 15;            // 0..15 -> cols tx*8..tx*8+7

    float acc[8][8];
#pragma unroll
    for (int i = 0; i < 8; i++)
#pragma unroll
        for (int j = 0; j < 8; j++) acc[i][j] = 0.f;

    for (int k0 = 0; k0 < K; k0 += BK) {
        int k = k0 + lr;
        // A tile
        {
            int m = bm + lc;
            if (k < K && m + 3 < M) {
                float4 vv = *reinterpret_cast<const float4*>(A + (long long)k * lda + m);
                As[lr][lc] = vv.x; As[lr][lc + 1] = vv.y; As[lr][lc + 2] = vv.z; As[lr][lc + 3] = vv.w;
            } else {
#pragma unroll
                for (int j = 0; j < 4; j++)
                    As[lr][lc + j] = (k < K && m + j < M) ? A[(long long)k * lda + m + j] : 0.f;
            }
        }
        // B tile
        {
            int n = bn + lc;
            if (k < K && n + 3 < N) {
                float4 vv = *reinterpret_cast<const float4*>(B + (long long)k * ldb + n);
                Bs[lr][lc] = vv.x; Bs[lr][lc + 1] = vv.y; Bs[lr][lc + 2] = vv.z; Bs[lr][lc + 3] = vv.w;
            } else {
#pragma unroll
                for (int j = 0; j < 4; j++)
                    Bs[lr][lc + j] = (k < K && n + j < N) ? B[(long long)k * ldb + n + j] : 0.f;
            }
        }
        __syncthreads();

#pragma unroll
        for (int kk = 0; kk < BK; kk++) {
            float4 a0 = *reinterpret_cast<float4*>(&As[kk][ty * 8]);
            float4 a1 = *reinterpret_cast<float4*>(&As[kk][ty * 8 + 4]);
            float4 b0 = *reinterpret_cast<float4*>(&Bs[kk][tx * 8]);
            float4 b1 = *reinterpret_cast<float4*>(&Bs[kk][tx * 8 + 4]);
            float a[8] = {a0.x, a0.y, a0.z, a0.w, a1.x, a1.y, a1.z, a1.w};
            float bb[8] = {b0.x, b0.y, b0.z, b0.w, b1.x, b1.y, b1.z, b1.w};
#pragma unroll
            for (int i = 0; i < 8; i++)
#pragma unroll
                for (int j = 0; j < 8; j++)
                    acc[i][j] = fmaf(a[i], bb[j], acc[i][j]);
        }
        __syncthreads();
    }

#pragma unroll
    for (int i = 0; i < 8; i++) {
        int m = bm + ty * 8 + i;
        if (m >= M) continue;
#pragma unroll
        for (int j = 0; j < 8; j++) {
            int n = bn + tx * 8 + j;
            if (n >= N) continue;
            float val = acc[i][j];
            if (ADD) val += Cadd[(long long)m * ldc + n];
            C[(long long)m * ldc + n] = val;
        }
    }
}

// ---------------- SPP (adaptive max pool pyramid 1/3/6/8) -----------------
__device__ __forceinline__ void spp_bounds(int s, int& r0, int& r1, int& c0, int& c1) {
    int o, i;
    if (s == 0)      { o = 1; i = 0; }
    else if (s < 10) { o = 3; i = s - 1; }
    else if (s < 46) { o = 6; i = s - 10; }
    else             { o = 8; i = s - 46; }
    int r = i / o, c = i % o;
    r0 = (r * HH) / o; r1 = ((r + 1) * HH + o - 1) / o;   // PyTorch adaptive bins
    c0 = (c * HH) / o; c1 = ((c + 1) * HH + o - 1) / o;
}

__global__ void spp_kernel() {
    int bid = blockIdx.x;                       // b*512 + ch
    const float* src = g_tg + (long long)bid * NN;
    __shared__ float t[NN];
    __shared__ float red[256];
    int tid = threadIdx.x;
    float mx = -INFINITY;
    for (int i = tid; i < NN; i += 256) {
        float vv = src[i];
        t[i] = vv;
        mx = fmaxf(mx, vv);
    }
    red[tid] = mx;
    __syncthreads();
    for (int st = 128; st > 0; st >>= 1) {
        if (tid < st) red[tid] = fmaxf(red[tid], red[tid + st]);
        __syncthreads();
    }
    if (tid < SS) {
        float out;
        if (tid == 0) {
            out = red[0];                       // 1x1 pool = global max
        } else {
            int r0, r1, c0, c1;
            spp_bounds(tid, r0, r1, c0, c1);
            out = -INFINITY;
            for (int r = r0; r < r1; r++)
                for (int c = c0; c < c1; c++)
                    out = fmaxf(out, t[r * HH + c]);
        }
        g_spp[(long long)bid * SS + tid] = out;
    }
}

// ---------------- kk = W_phi^T @ theta_spp , v = W_mask @ g_spp -----------
__global__ void kv_kernel(const float* __restrict__ wphi) {
    int b = blockIdx.x / SS, s = blockIdx.x % SS;
    __shared__ float th[ICN], gg[ICN];
    int tid = threadIdx.x;                      // 0..511
    {
        float vv = g_spp[((long long)(b * CC + tid)) * SS + s];
        if (tid < ICN) th[tid] = vv;
        else           gg[tid - ICN] = vv;
    }
    __syncthreads();
    float aK = 0.f, aV = 0.f;
    int c = tid;
#pragma unroll 4
    for (int ic = 0; ic < ICN; ic++) {
        aK = fmaf(wphi[ic * CC + c], th[ic], aK);
        aV = fmaf(g_wmT[ic * CC + c], gg[ic], aV);
    }
    g_kkT[((long long)(b * CC + c)) * SPAD + s] = aK;
    g_v[((long long)(b * SS + s)) * CC + c] = aV;
}

// ---------------- softmax over query axis (per (b,s) row of 4096) --------
__global__ void softmax_kernel() {
    int s = blockIdx.x, b = blockIdx.y;
    float* row = g_logits + ((long long)(b * SPAD + s)) * NN;
    __shared__ float red[256];
    int tid = threadIdx.x;
    float mx = -INFINITY;
    for (int i = tid; i < NN; i += 256) mx = fmaxf(mx, row[i]);
    red[tid] = mx;
    __syncthreads();
    for (int st = 128; st > 0; st >>= 1) {
        if (tid < st) red[tid] = fmaxf(red[tid], red[tid + st]);
        __syncthreads();
    }
    mx = red[0];
    __syncthreads();
    float sum = 0.f;
    for (int i = tid; i < NN; i += 256) {
        float e = __expf(row[i] - mx);
        row[i] = e;                              // store unnormalized exp
        sum += e;
    }
    red[tid] = sum;
    __syncthreads();
    for (int st = 128; st > 0; st >>= 1) {
        if (tid < st) red[tid] += red[tid + st];
        __syncthreads();
    }
    if (tid == 0) g_invsum[b * SS + s] = 1.0f / red[0];
}

// ---------------- fold 1/sumexp into v (float4: CC=512 divisible by 4) ----
__global__ void scalev_kernel() {
    int idx = blockIdx.x * 256 + threadIdx.x;   // float4 index
    if (idx < BB * SS * CC / 4) {
        float s = g_invsum[idx / (CC / 4)];     // (idx*4)/CC == b*SS+s
        float4* p = reinterpret_cast<float4*>(g_v) + idx;
        float4 vv = *p;
        vv.x *= s; vv.y *= s; vv.z *= s; vv.w *= s;
        *p = vv;
    }
}

// ---------------- launch --------------------------------------------------
extern "C" void kernel_launch(void* const* d_in, const int* in_sizes, int n_in,
                              void* d_out, int out_size) {
    const float* x     = (const float*)d_in[0];
    const float* y     = (const float*)d_in[1];
    const float* wphi  = (const float*)d_in[2];
    const float* wth   = (const float*)d_in[3];
    const float* wg    = (const float*)d_in[4];
    const float* wmask = (const float*)d_in[5];
    float* out = (float*)d_out;

    float *tg, *kkT, *v, *logits, *wT;
    cudaGetSymbolAddress((void**)&tg, g_tg);
    cudaGetSymbolAddress((void**)&kkT, g_kkT);
    cudaGetSymbolAddress((void**)&v, g_v);
    cudaGetSymbolAddress((void**)&logits, g_logits);
    cudaGetSymbolAddress((void**)&wT, g_wT);

    // 0. pack weights (wT = [theta;g]^T layout, wmT = w_mask^T)
    pack_kernel<<<(CC * CC + 255) / 256, 256>>>(wth, wg, wmask);

    // 1. fused theta/g conv: tg[b] = W_tg(512x512) @ y[b](512x4096)
    sgemm_k<0><<<dim3(NN / 128, CC / 128, BB), 256>>>(
        wT, y, nullptr, tg,
        CC, NN, CC, CC, NN, NN,
        0LL, (long long)CC * NN, 0LL, (long long)CC * NN);

    // 2. SPP pyramid max-pool
    spp_kernel<<<BB * CC, 256>>>();

    // 3. kk = W_phi^T @ theta_spp (stored [c, s_pad]); v = W_mask @ g_spp ([s, c])
    kv_kernel<<<BB * SS, CC>>>(wphi);

    // 4. logits[s,n] = sum_c kk[c,s] * x[c,n]   (S-major for query-axis softmax)
    sgemm_k<0><<<dim3(NN / 128, 1, BB), 256>>>(
        kkT, x, nullptr, logits,
        SS, NN, CC, SPAD, NN, NN,
        (long long)CC * SPAD, (long long)CC * NN, 0LL, (long long)SPAD * NN);

    // 5. softmax over n per (b,s); leaves exp() in logits, 1/sum in g_invsum
    softmax_kernel<<<dim3(SS, BB), 256>>>();

    // 6. fold 1/sum into v
    scalev_kernel<<<(BB * SS * CC / 4 + 255) / 256, 256>>>();

    // 7. out[c,n] = x[c,n] + sum_s v[s,c] * P[s,n]   (mask conv folded into v)
    sgemm_k<1><<<dim3(NN / 128, CC / 128, BB), 256>>>(
        v, logits, x, out,
        CC, NN, SS, CC, NN, NN,
        (long long)SS * CC, (long long)SPAD * NN, (long long)CC * NN, (long long)CC * NN);
}

// round 4
// speedup vs baseline: 2.0705x; 2.0705x over previous
#include <cuda_runtime.h>
#include <cuda_bf16.h>
#include <math.h>
#include <stdint.h>

// ---------------- problem constants ----------------
#define BB  16
#define CC  512
#define ICN 256
#define HH  64
#define NN  4096
#define SS  110
#define SP  128     // padded S

// ---------------- scratch (device globals) ----------------
__device__ float         g_tg[(long long)BB * CC * NN];        // theta/g conv out fp32 [B,512,N]
__device__ __nv_bfloat16 g_yTh[(long long)BB * NN * CC];       // y transposed bf16 hi [B,N,C]
__device__ __nv_bfloat16 g_yTl[(long long)BB * NN * CC];
__device__ __nv_bfloat16 g_xTh[(long long)BB * NN * CC];
__device__ __nv_bfloat16 g_xTl[(long long)BB * NN * CC];
__device__ __nv_bfloat16 g_wh[CC * CC];                        // [theta;g] weights [m,k]
__device__ __nv_bfloat16 g_wl[CC * CC];
__device__ __nv_bfloat16 g_wphiTh[CC * ICN];                   // w_phi^T [c, ic]
__device__ __nv_bfloat16 g_wphiTl[CC * ICN];
__device__ __nv_bfloat16 g_wmBh[CC * ICN];                     // w_mask [c, ic] (native)
__device__ __nv_bfloat16 g_wmBl[CC * ICN];
__device__ __nv_bfloat16 g_sppTh[BB * SP * CC];                // spp^T bf16 [B, s(pad), ch]
__device__ __nv_bfloat16 g_sppTl[BB * SP * CC];
__device__ float         g_kkf[BB * SP * CC];                  // kk fp32 [B, s, c]
__device__ __nv_bfloat16 g_kkh[BB * SP * CC];
__device__ __nv_bfloat16 g_kkl[BB * SP * CC];
__device__ float         g_v[BB * SP * CC];                    // v fp32 [B, s, c]
__device__ __nv_bfloat16 g_vTh[BB * CC * SP];                  // v^T bf16 [B, c, s]
__device__ __nv_bfloat16 g_vTl[BB * CC * SP];
__device__ float         g_logits[(long long)BB * SP * NN];    // [B, s(pad), n]
__device__ __nv_bfloat16 g_PTh[(long long)BB * NN * SP];       // exp(logits)^T [B, n, s]
__device__ __nv_bfloat16 g_PTl[(long long)BB * NN * SP];
__device__ float         g_max[BB * SS];
__device__ float         g_invsum[BB * SS];

// ---------------- helpers ----------------
__device__ __forceinline__ uint32_t smem_u32(const void* p) {
    uint32_t a;
    asm("{ .reg .u64 t; cvta.to.shared.u64 t, %1; cvt.u32.u64 %0, t; }" : "=r"(a) : "l"(p));
    return a;
}

#define CP_ASYNC16(saddr, gaddr) \
    asm volatile("cp.async.cg.shared.global [%0], [%1], 16;" :: "r"(saddr), "l"(gaddr))
#define CP_COMMIT() asm volatile("cp.async.commit_group;")
#define CP_WAIT1()  asm volatile("cp.async.wait_group 1;")

#define LDSM4(r0, r1, r2, r3, addr) \
    asm volatile("ldmatrix.sync.aligned.m8n8.x4.shared.b16 {%0,%1,%2,%3}, [%4];" \
                 : "=r"(r0), "=r"(r1), "=r"(r2), "=r"(r3) : "r"(addr))

#define MMA16816(d, a, b) \
    asm volatile("mma.sync.aligned.m16n8k16.row.col.f32.bf16.bf16.f32 " \
                 "{%0,%1,%2,%3}, {%4,%5,%6,%7}, {%8,%9}, {%0,%1,%2,%3};" \
                 : "+f"((d)[0]), "+f"((d)[1]), "+f"((d)[2]), "+f"((d)[3]) \
                 : "r"((a)[0]), "r"((a)[1]), "r"((a)[2]), "r"((a)[3]), \
                   "r"((b)[0]), "r"((b)[1]))

// ---------------- bf16x3 mma.sync GEMM ----------------
// C[m,n] = sum_k A[m,k]*B[n,k]  (both [rows, K] K-contiguous, bf16 hi/lo)
// BM=BN=128, BK=32, 8 warps (2x4, warp tile 64x32), padded smem rows (K32+8).
// 3-stage cp.async pipeline. All M,N multiples of 128, K multiple of 32.
#define LDP       40                 // padded row length (elements)
#define TILE_B    (128 * LDP * 2)    // 10240 bytes per operand tile
#define STAGE_B   (4 * TILE_B)       // Ah, Al, Bh, Bl
#define GSMEM_BYTES (3 * STAGE_B)    // 122880

template <int ADD>
__global__ void __launch_bounds__(256, 1)
gemm_mma(const __nv_bfloat16* __restrict__ Ah, const __nv_bfloat16* __restrict__ Al,
         long long sA, int lda,
         const __nv_bfloat16* __restrict__ Bh, const __nv_bfloat16* __restrict__ Bl,
         long long sB, int ldb,
         float* __restrict__ C, long long sC, int ldc,
         const float* __restrict__ Cadd, long long sAdd, int K)
{
    extern __shared__ char smem_raw[];
    const uint32_t sb = smem_u32(smem_raw);
    const int tid = threadIdx.x, wid = tid >> 5, lane = tid & 31;
    const int wm = wid & 1, wn = wid >> 1;       // 2 x 4 warp grid
    const int b = blockIdx.z;
    const int bm = blockIdx.y * 128, bn = blockIdx.x * 128;
    Ah += b * sA; Al += b * sA; Bh += b * sB; Bl += b * sB;
    C += b * sC;
    if (ADD) Cadd += b * sAdd;

    const int nkt = K >> 5;

    // cp.async loader for one k-tile into stage buffer
    auto load_stage = [&](int kt, int buf) {
        const uint32_t stg = sb + buf * STAGE_B;
        const int k0 = kt << 5;
#pragma unroll
        for (int i = 0; i < 2; i++) {
            int id = tid + (i << 8);             // 0..511
            int row = id >> 2, cq = (id & 3) << 3;   // cq in elements (8 each)
            uint32_t soff = row * (LDP * 2) + (cq << 1);
            CP_ASYNC16(stg + 0 * TILE_B + soff, (const char*)(Ah + (long long)(bm + row) * lda + k0 + cq));
            CP_ASYNC16(stg + 1 * TILE_B + soff, (const char*)(Al + (long long)(bm + row) * lda + k0 + cq));
            CP_ASYNC16(stg + 2 * TILE_B + soff, (const char*)(Bh + (long long)(bn + row) * ldb + k0 + cq));
            CP_ASYNC16(stg + 3 * TILE_B + soff, (const char*)(Bl + (long long)(bn + row) * ldb + k0 + cq));
        }
    };

    float acc[4][4][4];
#pragma unroll
    for (int mi = 0; mi < 4; mi++)
#pragma unroll
        for (int ni = 0; ni < 4; ni++)
#pragma unroll
            for (int r = 0; r < 4; r++) acc[mi][ni][r] = 0.f;

    // per-lane ldmatrix byte offsets within an operand tile
    const uint32_t a_lb = (wm * 64 + (lane & 15)) * (LDP * 2) + ((lane >> 4) << 4);
    const uint32_t b_lb = (wn * 32 + (lane & 7) + ((lane >> 4) << 3)) * (LDP * 2)
                        + (((lane >> 3) & 1) << 4);

    load_stage(0, 0); CP_COMMIT();
    if (nkt > 1) load_stage(1, 1);
    CP_COMMIT();

    int buf = 0;
    for (int kt = 0; kt < nkt; kt++) {
        CP_WAIT1();
        __syncthreads();
        if (kt + 2 < nkt) load_stage(kt + 2, (buf + 2) % 3);
        CP_COMMIT();

        const uint32_t stg = sb + buf * STAGE_B;
#pragma unroll
        for (int k16 = 0; k16 < 2; k16++) {
            const uint32_t kb = k16 << 5;        // 16 elements = 32 bytes
            uint32_t ah[4][4], al[4][4], bh[4][2], bl[4][2];
#pragma unroll
            for (int mi = 0; mi < 4; mi++) {
                uint32_t ad = stg + a_lb + mi * 16 * (LDP * 2) + kb;
                LDSM4(ah[mi][0], ah[mi][1], ah[mi][2], ah[mi][3], ad);
                LDSM4(al[mi][0], al[mi][1], al[mi][2], al[mi][3], ad + TILE_B);
            }
#pragma unroll
            for (int p = 0; p < 2; p++) {
                uint32_t bd = stg + 2 * TILE_B + b_lb + p * 16 * (LDP * 2) + kb;
                LDSM4(bh[2 * p][0], bh[2 * p][1], bh[2 * p + 1][0], bh[2 * p + 1][1], bd);
                LDSM4(bl[2 * p][0], bl[2 * p][1], bl[2 * p + 1][0], bl[2 * p + 1][1], bd + TILE_B);
            }
#pragma unroll
            for (int mi = 0; mi < 4; mi++)
#pragma unroll
                for (int ni = 0; ni < 4; ni++) {
                    MMA16816(acc[mi][ni], ah[mi], bh[ni]);
                    MMA16816(acc[mi][ni], ah[mi], bl[ni]);
                    MMA16816(acc[mi][ni], al[mi], bh[ni]);
                }
        }
        __syncthreads();
        buf = (buf + 1) % 3;
    }

    // epilogue: fragment layout row = lane/4 (+8), col = 2*(lane%4)
#pragma unroll
    for (int mi = 0; mi < 4; mi++) {
#pragma unroll
        for (int ni = 0; ni < 4; ni++) {
            int r0 = bm + wm * 64 + mi * 16 + (lane >> 2);
            int col = bn + wn * 32 + ni * 8 + ((lane & 3) << 1);
            float2 v01 = make_float2(acc[mi][ni][0], acc[mi][ni][1]);
            float2 v23 = make_float2(acc[mi][ni][2], acc[mi][ni][3]);
            if (ADD) {
                float2 a0 = *reinterpret_cast<const float2*>(Cadd + (long long)r0 * ldc + col);
                float2 a1 = *reinterpret_cast<const float2*>(Cadd + (long long)(r0 + 8) * ldc + col);
                v01.x += a0.x; v01.y += a0.y;
                v23.x += a1.x; v23.y += a1.y;
            }
            *reinterpret_cast<float2*>(C + (long long)r0 * ldc + col) = v01;
            *reinterpret_cast<float2*>(C + (long long)(r0 + 8) * ldc + col) = v23;
        }
    }
}

// ---------------- weight pack + pad zero ----------------
__global__ void pack_kernel(const float* __restrict__ wth, const float* __restrict__ wg,
                            const float* __restrict__ wphi, const float* __restrict__ wmask) {
    int idx = blockIdx.x * 256 + threadIdx.x;
    if (idx < CC * CC) {
        int m = idx / CC, k = idx % CC;
        float w = (m < ICN) ? wth[m * CC + k] : wg[(m - ICN) * CC + k];
        __nv_bfloat16 h = __float2bfloat16(w);
        g_wh[idx] = h;
        g_wl[idx] = __float2bfloat16(w - __bfloat162float(h));
    }
    if (idx < CC * ICN) {
        int c = idx / ICN, ic = idx % ICN;
        float wp = wphi[ic * CC + c];
        __nv_bfloat16 h = __float2bfloat16(wp);
        g_wphiTh[idx] = h;
        g_wphiTl[idx] = __float2bfloat16(wp - __bfloat162float(h));
        float wm = wmask[idx];            // wmask is [c, ic] row-major already
        __nv_bfloat16 hm = __float2bfloat16(wm);
        g_wmBh[idx] = hm;
        g_wmBl[idx] = __float2bfloat16(wm - __bfloat162float(hm));
    }
    if (idx < BB * (SP - SS) * CC) {      // zero spp^T pad rows every launch
        int b = idx / ((SP - SS) * CC);
        int rem = idx % ((SP - SS) * CC);
        int s = SS + rem / CC, c = rem % CC;
        long long o = ((long long)(b * SP) + s) * CC + c;
        g_sppTh[o] = __float2bfloat16(0.f);
        g_sppTl[o] = __float2bfloat16(0.f);
    }
}

// ---------------- fp32 [C, N] -> bf16 hi/lo [N, C] (transpose-convert) ----
__global__ void tconv_kernel(const float* __restrict__ src,
                             __nv_bfloat16* __restrict__ dh, __nv_bfloat16* __restrict__ dl) {
    __shared__ float sm[32][33];
    int n0 = blockIdx.x * 32, c0 = blockIdx.y * 32, b = blockIdx.z;
    int tx = threadIdx.x, ty = threadIdx.y;
    src += (long long)b * CC * NN;
#pragma unroll
    for (int r = 0; r < 4; r++)
        sm[ty + 8 * r][tx] = src[(long long)(c0 + ty + 8 * r) * NN + n0 + tx];
    __syncthreads();
#pragma unroll
    for (int r = 0; r < 4; r++) {
        int n = n0 + ty + 8 * r, c = c0 + tx;
        float v = sm[tx][ty + 8 * r];
        __nv_bfloat16 h = __float2bfloat16(v);
        long long o = ((long long)b * NN + n) * CC + c;
        dh[o] = h;
        dl[o] = __float2bfloat16(v - __bfloat162float(h));
    }
}

// ---------------- SPP pyramid (1/3/6/8) -> bf16 hi/lo transposed ----------
__device__ __forceinline__ void spp_bounds(int s, int& r0, int& r1, int& c0, int& c1) {
    int o, i;
    if (s == 0)      { o = 1; i = 0; }
    else if (s < 10) { o = 3; i = s - 1; }
    else if (s < 46) { o = 6; i = s - 10; }
    else             { o = 8; i = s - 46; }
    int r = i / o, c = i % o;
    r0 = (r * HH) / o; r1 = ((r + 1) * HH + o - 1) / o;
    c0 = (c * HH) / o; c1 = ((c + 1) * HH + o - 1) / o;
}

__global__ void spp_kernel() {
    int bid = blockIdx.x;                       // b*512 + ch
    int b = bid / CC, ch = bid % CC;
    const float* src = g_tg + (long long)bid * NN;
    __shared__ float t[NN];
    __shared__ float red[256];
    int tid = threadIdx.x;
    float mx = -INFINITY;
    for (int i = tid; i < NN; i += 256) {
        float vv = src[i];
        t[i] = vv;
        mx = fmaxf(mx, vv);
    }
    red[tid] = mx;
    __syncthreads();
    for (int st = 128; st > 0; st >>= 1) {
        if (tid < st) red[tid] = fmaxf(red[tid], red[tid + st]);
        __syncthreads();
    }
    if (tid < SS) {
        float out;
        if (tid == 0) out = red[0];
        else {
            int r0, r1, c0, c1;
            spp_bounds(tid, r0, r1, c0, c1);
            out = -INFINITY;
            for (int r = r0; r < r1; r++)
                for (int c = c0; c < c1; c++)
                    out = fmaxf(out, t[r * HH + c]);
        }
        __nv_bfloat16 h = __float2bfloat16(out);
        long long o = ((long long)(b * SP) + tid) * CC + ch;
        g_sppTh[o] = h;
        g_sppTl[o] = __float2bfloat16(out - __bfloat162float(h));
    }
}

// ---------------- kk fp32 -> bf16 hi/lo ----------------
__global__ void kkcvt_kernel() {
    int gid = blockIdx.x * 256 + threadIdx.x;
    if (gid < BB * SP * CC) {
        float v = g_kkf[gid];
        __nv_bfloat16 h = __float2bfloat16(v);
        g_kkh[gid] = h;
        g_kkl[gid] = __float2bfloat16(v - __bfloat162float(h));
    }
}

// ---------------- row stats: max + 1/sum(exp) per (b,s) ----------------
__global__ void rowstat_kernel() {
    int s = blockIdx.x, b = blockIdx.y;
    const float* row = g_logits + ((long long)(b * SP + s)) * NN;
    __shared__ float t[NN];
    __shared__ float red[256];
    int tid = threadIdx.x;
    float mx = -INFINITY;
    for (int i = tid; i < NN; i += 256) {
        float v = row[i];
        t[i] = v;
        mx = fmaxf(mx, v);
    }
    red[tid] = mx;
    __syncthreads();
    for (int st = 128; st > 0; st >>= 1) {
        if (tid < st) red[tid] = fmaxf(red[tid], red[tid + st]);
        __syncthreads();
    }
    mx = red[0];
    __syncthreads();
    float sum = 0.f;
    for (int i = tid; i < NN; i += 256) sum += __expf(t[i] - mx);
    red[tid] = sum;
    __syncthreads();
    for (int st = 128; st > 0; st >>= 1) {
        if (tid < st) red[tid] += red[tid + st];
        __syncthreads();
    }
    if (tid == 0) {
        g_max[b * SS + s] = mx;
        g_invsum[b * SS + s] = 1.0f / red[0];
    }
}

// ---------------- exp + transpose: logits [s,n] -> PT bf16 [n,s] ----------
__global__ void texp_kernel() {
    __shared__ float sm[32][SP + 1];
    __shared__ float gmx[SP];
    int b = blockIdx.y, n0 = blockIdx.x * 32;
    int tid = threadIdx.x;
    if (tid < SS) gmx[tid] = g_max[b * SS + tid];
    __syncthreads();
    int tx = tid & 31, ty = tid >> 5;          // ty 0..7
#pragma unroll
    for (int r = 0; r < 16; r++) {
        int s = ty + (r << 3);
        float e = 0.f;
        if (s < SS)
            e = __expf(g_logits[((long long)(b * SP + s)) * NN + n0 + tx] - gmx[s]);
        sm[tx][s] = e;
    }
    __syncthreads();
#pragma unroll
    for (int w = 0; w < 16; w++) {
        int idx = tid + (w << 8);
        int nl = idx >> 7, s = idx & 127;
        float v = sm[nl][s];
        __nv_bfloat16 h = __float2bfloat16(v);
        long long o = ((long long)(b * NN) + n0 + nl) * SP + s;
        g_PTh[o] = h;
        g_PTl[o] = __float2bfloat16(v - __bfloat162float(h));
    }
}

// ---------------- v [s,c] * invsum -> vT bf16 hi/lo [c,s] ----------------
__global__ void vt_kernel() {
    int gid = blockIdx.x * 256 + threadIdx.x;
    if (gid >= BB * CC * SP) return;
    int b = gid >> 16;                // CC*SP = 65536
    int rem = gid & 65535;
    int c = rem >> 7, s = rem & 127;
    float val = 0.f;
    if (s < SS)
        val = g_v[((long long)(b * SP + s)) * CC + c] * g_invsum[b * SS + s];
    __nv_bfloat16 h = __float2bfloat16(val);
    long long o = ((long long)b * CC + c) * SP + s;
    g_vTh[o] = h;
    g_vTl[o] = __float2bfloat16(val - __bfloat162float(h));
}

// ---------------- launch ----------------
extern "C" void kernel_launch(void* const* d_in, const int* in_sizes, int n_in,
                              void* d_out, int out_size) {
    const float* x     = (const float*)d_in[0];
    const float* y     = (const float*)d_in[1];
    const float* wphi  = (const float*)d_in[2];
    const float* wth   = (const float*)d_in[3];
    const float* wg    = (const float*)d_in[4];
    const float* wmask = (const float*)d_in[5];
    float* out = (float*)d_out;

    cudaFuncSetAttribute(gemm_mma<0>, cudaFuncAttributeMaxDynamicSharedMemorySize, GSMEM_BYTES);
    cudaFuncSetAttribute(gemm_mma<1>, cudaFuncAttributeMaxDynamicSharedMemorySize, GSMEM_BYTES);

    float *tg, *kkf, *v, *logits;
    __nv_bfloat16 *yTh, *yTl, *xTh, *xTl, *wh, *wl, *wpTh, *wpTl, *wmBh, *wmBl;
    __nv_bfloat16 *spTh, *spTl, *kkh, *kkl, *vTh, *vTl, *PTh, *PTl;
    cudaGetSymbolAddress((void**)&tg, g_tg);
    cudaGetSymbolAddress((void**)&kkf, g_kkf);
    cudaGetSymbolAddress((void**)&v, g_v);
    cudaGetSymbolAddress((void**)&logits, g_logits);
    cudaGetSymbolAddress((void**)&yTh, g_yTh);   cudaGetSymbolAddress((void**)&yTl, g_yTl);
    cudaGetSymbolAddress((void**)&xTh, g_xTh);   cudaGetSymbolAddress((void**)&xTl, g_xTl);
    cudaGetSymbolAddress((void**)&wh, g_wh);     cudaGetSymbolAddress((void**)&wl, g_wl);
    cudaGetSymbolAddress((void**)&wpTh, g_wphiTh); cudaGetSymbolAddress((void**)&wpTl, g_wphiTl);
    cudaGetSymbolAddress((void**)&wmBh, g_wmBh); cudaGetSymbolAddress((void**)&wmBl, g_wmBl);
    cudaGetSymbolAddress((void**)&spTh, g_sppTh); cudaGetSymbolAddress((void**)&spTl, g_sppTl);
    cudaGetSymbolAddress((void**)&kkh, g_kkh);   cudaGetSymbolAddress((void**)&kkl, g_kkl);
    cudaGetSymbolAddress((void**)&vTh, g_vTh);   cudaGetSymbolAddress((void**)&vTl, g_vTl);
    cudaGetSymbolAddress((void**)&PTh, g_PTh);   cudaGetSymbolAddress((void**)&PTl, g_PTl);

    // 0. pack weights, zero spp pad rows
    pack_kernel<<<(CC * CC + 255) / 256, 256>>>(wth, wg, wphi, wmask);

    // 1. transpose-convert y and x to bf16 hi/lo [N, C]
    tconv_kernel<<<dim3(NN / 32, CC / 32, BB), dim3(32, 8)>>>(y, yTh, yTl);
    tconv_kernel<<<dim3(NN / 32, CC / 32, BB), dim3(32, 8)>>>(x, xTh, xTl);

    // 2. tg[m,n] = sum_c W_tg[m,c] * y[c,n]     (M=512, N=4096, K=512)
    gemm_mma<0><<<dim3(NN / 128, CC / 128, BB), 256, GSMEM_BYTES>>>(
        wh, wl, 0LL, CC, yTh, yTl, (long long)NN * CC, CC,
        tg, (long long)CC * NN, NN, nullptr, 0LL, CC);

    // 3. SPP pyramid -> spp^T bf16 hi/lo [B, s, ch]
    spp_kernel<<<BB * CC, 256>>>();

    // 4. kk[s,c] = sum_ic sppT[s,ic(theta)] * wphiT[c,ic]   (M=128, N=512, K=256)
    gemm_mma<0><<<dim3(CC / 128, 1, BB), 256, GSMEM_BYTES>>>(
        spTh, spTl, (long long)SP * CC, CC, wpTh, wpTl, 0LL, ICN,
        kkf, (long long)SP * CC, CC, nullptr, 0LL, ICN);
    kkcvt_kernel<<<(BB * SP * CC + 255) / 256, 256>>>();

    // 5. v[s,c] = sum_ic sppT[s, 256+ic(g)] * wmask[c,ic]   (M=128, N=512, K=256)
    gemm_mma<0><<<dim3(CC / 128, 1, BB), 256, GSMEM_BYTES>>>(
        spTh + ICN, spTl + ICN, (long long)SP * CC, CC, wmBh, wmBl, 0LL, ICN,
        v, (long long)SP * CC, CC, nullptr, 0LL, ICN);

    // 6. logits[s,n] = sum_c kk[s,c] * x[c,n]   (M=128, N=4096, K=512)
    gemm_mma<0><<<dim3(NN / 128, 1, BB), 256, GSMEM_BYTES>>>(
        kkh, kkl, (long long)SP * CC, CC, xTh, xTl, (long long)NN * CC, CC,
        logits, (long long)SP * NN, NN, nullptr, 0LL, CC);

    // 7. per-(b,s) max + 1/sum(exp)
    rowstat_kernel<<<dim3(SS, BB), 256>>>();

    // 8. exp + transpose -> PT bf16 hi/lo [n, s]
    texp_kernel<<<dim3(NN / 32, BB), 256>>>();

    // 9. scale v by invsum, transpose -> vT bf16 hi/lo [c, s]
    vt_kernel<<<(BB * CC * SP + 255) / 256, 256>>>();

    // 10. out[c,n] = x[c,n] + sum_s vT[c,s] * PT[n,s]   (M=512, N=4096, K=128)
    gemm_mma<1><<<dim3(NN / 128, CC / 128, BB), 256, GSMEM_BYTES>>>(
        vTh, vTl, (long long)CC * SP, SP, PTh, PTl, (long long)NN * SP, SP,
        out, (long long)CC * NN, NN, x, (long long)CC * NN, SP);
}

// round 5
// speedup vs baseline: 2.3206x; 1.1208x over previous
#include <cuda_runtime.h>
#include <cuda_bf16.h>
#include <math.h>
#include <stdint.h>

// ---------------- problem constants ----------------
#define BB  16
#define CC  512
#define ICN 256
#define HH  64
#define NN  4096
#define SS  110
#define SP  128     // padded S

// ---------------- scratch (device globals) ----------------
__device__ float         g_tg[(long long)BB * CC * NN];        // theta/g conv out fp32 [B,512,N]
__device__ __nv_bfloat16 g_yTh[(long long)BB * NN * CC];       // y transposed bf16 hi [B,N,C]
__device__ __nv_bfloat16 g_yTl[(long long)BB * NN * CC];
__device__ __nv_bfloat16 g_xTh[(long long)BB * NN * CC];
__device__ __nv_bfloat16 g_xTl[(long long)BB * NN * CC];
__device__ __nv_bfloat16 g_wh[CC * CC];                        // [theta;g] weights [m,k]
__device__ __nv_bfloat16 g_wl[CC * CC];
__device__ __nv_bfloat16 g_wphiTh[CC * ICN];                   // w_phi^T [c, ic]
__device__ __nv_bfloat16 g_wphiTl[CC * ICN];
__device__ __nv_bfloat16 g_wmBh[CC * ICN];                     // w_mask [c, ic] (native)
__device__ __nv_bfloat16 g_wmBl[CC * ICN];
__device__ __nv_bfloat16 g_sppTh[BB * SP * CC];                // spp^T bf16 [B, s(pad), ch]
__device__ __nv_bfloat16 g_sppTl[BB * SP * CC];
__device__ float         g_kkf[BB * SP * CC];                  // kk fp32 [B, s, c]
__device__ __nv_bfloat16 g_kkh[BB * SP * CC];
__device__ __nv_bfloat16 g_kkl[BB * SP * CC];
__device__ float         g_v[BB * SP * CC];                    // v fp32 [B, s, c]
__device__ __nv_bfloat16 g_vTh[BB * CC * SP];                  // v^T bf16 [B, c, s]
__device__ __nv_bfloat16 g_vTl[BB * CC * SP];
__device__ float         g_logits[(long long)BB * SP * NN];    // [B, s(pad), n]
__device__ __nv_bfloat16 g_PTh[(long long)BB * NN * SP];       // exp(logits)^T [B, n, s]
__device__ __nv_bfloat16 g_PTl[(long long)BB * NN * SP];
__device__ float         g_max[BB * SS];
__device__ float         g_invsum[BB * SS];

// ---------------- helpers ----------------
__device__ __forceinline__ uint32_t smem_u32(const void* p) {
    uint32_t a;
    asm("{ .reg .u64 t; cvta.to.shared.u64 t, %1; cvt.u32.u64 %0, t; }" : "=r"(a) : "l"(p));
    return a;
}

#define CP_ASYNC16(saddr, gaddr) \
    asm volatile("cp.async.cg.shared.global [%0], [%1], 16;" :: "r"(saddr), "l"(gaddr))
#define CP_COMMIT() asm volatile("cp.async.commit_group;")
#define CP_WAIT1()  asm volatile("cp.async.wait_group 1;")
#define CP_WAIT0()  asm volatile("cp.async.wait_group 0;")

#define LDSM4(r0, r1, r2, r3, addr) \
    asm volatile("ldmatrix.sync.aligned.m8n8.x4.shared.b16 {%0,%1,%2,%3}, [%4];" \
                 : "=r"(r0), "=r"(r1), "=r"(r2), "=r"(r3) : "r"(addr))

#define MMA16816(d, a, b) \
    asm volatile("mma.sync.aligned.m16n8k16.row.col.f32.bf16.bf16.f32 " \
                 "{%0,%1,%2,%3}, {%4,%5,%6,%7}, {%8,%9}, {%0,%1,%2,%3};" \
                 : "+f"((d)[0]), "+f"((d)[1]), "+f"((d)[2]), "+f"((d)[3]) \
                 : "r"((a)[0]), "r"((a)[1]), "r"((a)[2]), "r"((a)[3]), \
                   "r"((b)[0]), "r"((b)[1]))

// ---------------- bf16x3 mma.sync GEMM ----------------
// C[m,n] = sum_k A[m,k]*B[n,k]  (both [rows, K] K-contiguous, bf16 hi/lo)
// BM=BN=128, BK=32, 8 warps (2x4, warp tile 64x32), padded smem rows (K32+8).
// 2-stage cp.async double buffer; 2 CTAs/SM for cross-CTA latency hiding.
#define LDP       40                 // padded row length (elements)
#define TILE_B    (128 * LDP * 2)    // 10240 bytes per operand tile
#define STAGE_B   (4 * TILE_B)       // Ah, Al, Bh, Bl
#define GSMEM_BYTES (2 * STAGE_B)    // 81920

template <int ADD>
__global__ void __launch_bounds__(256, 2)
gemm_mma(const __nv_bfloat16* __restrict__ Ah, const __nv_bfloat16* __restrict__ Al,
         long long sA, int lda,
         const __nv_bfloat16* __restrict__ Bh, const __nv_bfloat16* __restrict__ Bl,
         long long sB, int ldb,
         float* __restrict__ C, long long sC, int ldc,
         const float* __restrict__ Cadd, long long sAdd, int K)
{
    extern __shared__ char smem_raw[];
    const uint32_t sb = smem_u32(smem_raw);
    const int tid = threadIdx.x, wid = tid >> 5, lane = tid & 31;
    const int wm = wid & 1, wn = wid >> 1;       // 2 x 4 warp grid
    const int b = blockIdx.z;
    const int bm = blockIdx.y * 128, bn = blockIdx.x * 128;
    Ah += b * sA; Al += b * sA; Bh += b * sB; Bl += b * sB;
    C += b * sC;
    if (ADD) Cadd += b * sAdd;

    const int nkt = K >> 5;

    // cp.async loader for one k-tile into stage buffer
    auto load_stage = [&](int kt, int buf) {
        const uint32_t stg = sb + buf * STAGE_B;
        const int k0 = kt << 5;
#pragma unroll
        for (int i = 0; i < 2; i++) {
            int id = tid + (i << 8);             // 0..511
            int row = id >> 2, cq = (id & 3) << 3;   // cq in elements (8 each)
            uint32_t soff = row * (LDP * 2) + (cq << 1);
            CP_ASYNC16(stg + 0 * TILE_B + soff, (const char*)(Ah + (long long)(bm + row) * lda + k0 + cq));
            CP_ASYNC16(stg + 1 * TILE_B + soff, (const char*)(Al + (long long)(bm + row) * lda + k0 + cq));
            CP_ASYNC16(stg + 2 * TILE_B + soff, (const char*)(Bh + (long long)(bn + row) * ldb + k0 + cq));
            CP_ASYNC16(stg + 3 * TILE_B + soff, (const char*)(Bl + (long long)(bn + row) * ldb + k0 + cq));
        }
    };

    float acc[4][4][4];
#pragma unroll
    for (int mi = 0; mi < 4; mi++)
#pragma unroll
        for (int ni = 0; ni < 4; ni++)
#pragma unroll
            for (int r = 0; r < 4; r++) acc[mi][ni][r] = 0.f;

    // per-lane ldmatrix byte offsets within an operand tile
    const uint32_t a_lb = (wm * 64 + (lane & 15)) * (LDP * 2) + ((lane >> 4) << 4);
    const uint32_t b_lb = (wn * 32 + (lane & 7) + ((lane >> 4) << 3)) * (LDP * 2)
                        + (((lane >> 3) & 1) << 4);

    load_stage(0, 0); CP_COMMIT();

    for (int kt = 0; kt < nkt; kt++) {
        const int buf = kt & 1;
        if (kt + 1 < nkt) {
            load_stage(kt + 1, buf ^ 1); CP_COMMIT();
            CP_WAIT1();
        } else {
            CP_WAIT0();
        }
        __syncthreads();

        const uint32_t stg = sb + buf * STAGE_B;
#pragma unroll
        for (int k16 = 0; k16 < 2; k16++) {
            const uint32_t kb = k16 << 5;        // 16 elements = 32 bytes
            uint32_t bh[4][2], bl[4][2];
#pragma unroll
            for (int p = 0; p < 2; p++) {
                uint32_t bd = stg + 2 * TILE_B + b_lb + p * 16 * (LDP * 2) + kb;
                LDSM4(bh[2 * p][0], bh[2 * p][1], bh[2 * p + 1][0], bh[2 * p + 1][1], bd);
                LDSM4(bl[2 * p][0], bl[2 * p][1], bl[2 * p + 1][0], bl[2 * p + 1][1], bd + TILE_B);
            }
#pragma unroll
            for (int mi = 0; mi < 4; mi++) {
                uint32_t ah[4], al[4];
                uint32_t ad = stg + a_lb + mi * 16 * (LDP * 2) + kb;
                LDSM4(ah[0], ah[1], ah[2], ah[3], ad);
                LDSM4(al[0], al[1], al[2], al[3], ad + TILE_B);
#pragma unroll
                for (int ni = 0; ni < 4; ni++) {
                    MMA16816(acc[mi][ni], ah, bh[ni]);
                    MMA16816(acc[mi][ni], ah, bl[ni]);
                    MMA16816(acc[mi][ni], al, bh[ni]);
                }
            }
        }
        __syncthreads();
    }

    // epilogue: fragment layout row = lane/4 (+8), col = 2*(lane%4)
#pragma unroll
    for (int mi = 0; mi < 4; mi++) {
#pragma unroll
        for (int ni = 0; ni < 4; ni++) {
            int r0 = bm + wm * 64 + mi * 16 + (lane >> 2);
            int col = bn + wn * 32 + ni * 8 + ((lane & 3) << 1);
            float2 v01 = make_float2(acc[mi][ni][0], acc[mi][ni][1]);
            float2 v23 = make_float2(acc[mi][ni][2], acc[mi][ni][3]);
            if (ADD) {
                float2 a0 = *reinterpret_cast<const float2*>(Cadd + (long long)r0 * ldc + col);
                float2 a1 = *reinterpret_cast<const float2*>(Cadd + (long long)(r0 + 8) * ldc + col);
                v01.x += a0.x; v01.y += a0.y;
                v23.x += a1.x; v23.y += a1.y;
            }
            *reinterpret_cast<float2*>(C + (long long)r0 * ldc + col) = v01;
            *reinterpret_cast<float2*>(C + (long long)(r0 + 8) * ldc + col) = v23;
        }
    }
}

// ---------------- weight pack + pad zero ----------------
__global__ void pack_kernel(const float* __restrict__ wth, const float* __restrict__ wg,
                            const float* __restrict__ wphi, const float* __restrict__ wmask) {
    int idx = blockIdx.x * 256 + threadIdx.x;
    if (idx < CC * CC) {
        int m = idx / CC, k = idx % CC;
        float w = (m < ICN) ? wth[m * CC + k] : wg[(m - ICN) * CC + k];
        __nv_bfloat16 h = __float2bfloat16(w);
        g_wh[idx] = h;
        g_wl[idx] = __float2bfloat16(w - __bfloat162float(h));
    }
    if (idx < CC * ICN) {
        int c = idx / ICN, ic = idx % ICN;
        float wp = wphi[ic * CC + c];
        __nv_bfloat16 h = __float2bfloat16(wp);
        g_wphiTh[idx] = h;
        g_wphiTl[idx] = __float2bfloat16(wp - __bfloat162float(h));
        float wm = wmask[idx];            // wmask is [c, ic] row-major already
        __nv_bfloat16 hm = __float2bfloat16(wm);
        g_wmBh[idx] = hm;
        g_wmBl[idx] = __float2bfloat16(wm - __bfloat162float(hm));
    }
    if (idx < BB * (SP - SS) * CC) {      // zero spp^T pad rows every launch
        int b = idx / ((SP - SS) * CC);
        int rem = idx % ((SP - SS) * CC);
        int s = SS + rem / CC, c = rem % CC;
        long long o = ((long long)(b * SP) + s) * CC + c;
        g_sppTh[o] = __float2bfloat16(0.f);
        g_sppTl[o] = __float2bfloat16(0.f);
    }
}

// ---------------- fp32 [C, N] -> bf16 hi/lo [N, C] (transpose-convert) ----
__global__ void tconv_kernel(const float* __restrict__ src,
                             __nv_bfloat16* __restrict__ dh, __nv_bfloat16* __restrict__ dl) {
    __shared__ float sm[32][33];
    int n0 = blockIdx.x * 32, c0 = blockIdx.y * 32, b = blockIdx.z;
    int tx = threadIdx.x, ty = threadIdx.y;
    src += (long long)b * CC * NN;
#pragma unroll
    for (int r = 0; r < 4; r++)
        sm[ty + 8 * r][tx] = src[(long long)(c0 + ty + 8 * r) * NN + n0 + tx];
    __syncthreads();
#pragma unroll
    for (int r = 0; r < 4; r++) {
        int n = n0 + ty + 8 * r, c = c0 + tx;
        float v = sm[tx][ty + 8 * r];
        __nv_bfloat16 h = __float2bfloat16(v);
        long long o = ((long long)b * NN + n) * CC + c;
        dh[o] = h;
        dl[o] = __float2bfloat16(v - __bfloat162float(h));
    }
}

// ---------------- SPP pyramid (1/3/6/8) -> bf16 hi/lo transposed ----------
__device__ __forceinline__ void spp_bounds(int s, int& r0, int& r1, int& c0, int& c1) {
    int o, i;
    if (s == 0)      { o = 1; i = 0; }
    else if (s < 10) { o = 3; i = s - 1; }
    else if (s < 46) { o = 6; i = s - 10; }
    else             { o = 8; i = s - 46; }
    int r = i / o, c = i % o;
    r0 = (r * HH) / o; r1 = ((r + 1) * HH + o - 1) / o;
    c0 = (c * HH) / o; c1 = ((c + 1) * HH + o - 1) / o;
}

__global__ void spp_kernel() {
    int bid = blockIdx.x;                       // b*512 + ch
    int b = bid / CC, ch = bid % CC;
    const float* src = g_tg + (long long)bid * NN;
    __shared__ float t[NN];
    __shared__ float red[256];
    int tid = threadIdx.x;
    float mx = -INFINITY;
    for (int i = tid; i < NN; i += 256) {
        float vv = src[i];
        t[i] = vv;
        mx = fmaxf(mx, vv);
    }
    red[tid] = mx;
    __syncthreads();
    for (int st = 128; st > 0; st >>= 1) {
        if (tid < st) red[tid] = fmaxf(red[tid], red[tid + st]);
        __syncthreads();
    }
    if (tid < SS) {
        float out;
        if (tid == 0) out = red[0];
        else {
            int r0, r1, c0, c1;
            spp_bounds(tid, r0, r1, c0, c1);
            out = -INFINITY;
            for (int r = r0; r < r1; r++)
                for (int c = c0; c < c1; c++)
                    out = fmaxf(out, t[r * HH + c]);
        }
        __nv_bfloat16 h = __float2bfloat16(out);
        long long o = ((long long)(b * SP) + tid) * CC + ch;
        g_sppTh[o] = h;
        g_sppTl[o] = __float2bfloat16(out - __bfloat162float(h));
    }
}

// ---------------- kk fp32 -> bf16 hi/lo ----------------
__global__ void kkcvt_kernel() {
    int gid = blockIdx.x * 256 + threadIdx.x;
    if (gid < BB * SP * CC) {
        float v = g_kkf[gid];
        __nv_bfloat16 h = __float2bfloat16(v);
        g_kkh[gid] = h;
        g_kkl[gid] = __float2bfloat16(v - __bfloat162float(h));
    }
}

// ---------------- row stats: max + 1/sum(exp) per (b,s) ----------------
__global__ void rowstat_kernel() {
    int s = blockIdx.x, b = blockIdx.y;
    const float* row = g_logits + ((long long)(b * SP + s)) * NN;
    __shared__ float t[NN];
    __shared__ float red[256];
    int tid = threadIdx.x;
    float mx = -INFINITY;
    for (int i = tid; i < NN; i += 256) {
        float v = row[i];
        t[i] = v;
        mx = fmaxf(mx, v);
    }
    red[tid] = mx;
    __syncthreads();
    for (int st = 128; st > 0; st >>= 1) {
        if (tid < st) red[tid] = fmaxf(red[tid], red[tid + st]);
        __syncthreads();
    }
    mx = red[0];
    __syncthreads();
    float sum = 0.f;
    for (int i = tid; i < NN; i += 256) sum += __expf(t[i] - mx);
    red[tid] = sum;
    __syncthreads();
    for (int st = 128; st > 0; st >>= 1) {
        if (tid < st) red[tid] += red[tid + st];
        __syncthreads();
    }
    if (tid == 0) {
        g_max[b * SS + s] = mx;
        g_invsum[b * SS + s] = 1.0f / red[0];
    }
}

// ---------------- exp + transpose: logits [s,n] -> PT bf16 [n,s] ----------
__global__ void texp_kernel() {
    __shared__ float sm[32][SP + 1];
    __shared__ float gmx[SP];
    int b = blockIdx.y, n0 = blockIdx.x * 32;
    int tid = threadIdx.x;
    if (tid < SS) gmx[tid] = g_max[b * SS + tid];
    __syncthreads();
    int tx = tid & 31, ty = tid >> 5;          // ty 0..7
#pragma unroll
    for (int r = 0; r < 16; r++) {
        int s = ty + (r << 3);
        float e = 0.f;
        if (s < SS)
            e = __expf(g_logits[((long long)(b * SP + s)) * NN + n0 + tx] - gmx[s]);
        sm[tx][s] = e;
    }
    __syncthreads();
#pragma unroll
    for (int w = 0; w < 16; w++) {
        int idx = tid + (w << 8);
        int nl = idx >> 7, s = idx & 127;
        float v = sm[nl][s];
        __nv_bfloat16 h = __float2bfloat16(v);
        long long o = ((long long)(b * NN) + n0 + nl) * SP + s;
        g_PTh[o] = h;
        g_PTl[o] = __float2bfloat16(v - __bfloat162float(h));
    }
}

// ---------------- v [s,c] * invsum -> vT bf16 hi/lo [c,s] ----------------
__global__ void vt_kernel() {
    int gid = blockIdx.x * 256 + threadIdx.x;
    if (gid >= BB * CC * SP) return;
    int b = gid >> 16;                // CC*SP = 65536
    int rem = gid & 65535;
    int c = rem >> 7, s = rem & 127;
    float val = 0.f;
    if (s < SS)
        val = g_v[((long long)(b * SP + s)) * CC + c] * g_invsum[b * SS + s];
    __nv_bfloat16 h = __float2bfloat16(val);
    long long o = ((long long)b * CC + c) * SP + s;
    g_vTh[o] = h;
    g_vTl[o] = __float2bfloat16(val - __bfloat162float(h));
}

// ---------------- launch ----------------
extern "C" void kernel_launch(void* const* d_in, const int* in_sizes, int n_in,
                              void* d_out, int out_size) {
    const float* x     = (const float*)d_in[0];
    const float* y     = (const float*)d_in[1];
    const float* wphi  = (const float*)d_in[2];
    const float* wth   = (const float*)d_in[3];
    const float* wg    = (const float*)d_in[4];
    const float* wmask = (const float*)d_in[5];
    float* out = (float*)d_out;

    cudaFuncSetAttribute(gemm_mma<0>, cudaFuncAttributeMaxDynamicSharedMemorySize, GSMEM_BYTES);
    cudaFuncSetAttribute(gemm_mma<1>, cudaFuncAttributeMaxDynamicSharedMemorySize, GSMEM_BYTES);

    float *tg, *kkf, *v, *logits;
    __nv_bfloat16 *yTh, *yTl, *xTh, *xTl, *wh, *wl, *wpTh, *wpTl, *wmBh, *wmBl;
    __nv_bfloat16 *spTh, *spTl, *kkh, *kkl, *vTh, *vTl, *PTh, *PTl;
    cudaGetSymbolAddress((void**)&tg, g_tg);
    cudaGetSymbolAddress((void**)&kkf, g_kkf);
    cudaGetSymbolAddress((void**)&v, g_v);
    cudaGetSymbolAddress((void**)&logits, g_logits);
    cudaGetSymbolAddress((void**)&yTh, g_yTh);   cudaGetSymbolAddress((void**)&yTl, g_yTl);
    cudaGetSymbolAddress((void**)&xTh, g_xTh);   cudaGetSymbolAddress((void**)&xTl, g_xTl);
    cudaGetSymbolAddress((void**)&wh, g_wh);     cudaGetSymbolAddress((void**)&wl, g_wl);
    cudaGetSymbolAddress((void**)&wpTh, g_wphiTh); cudaGetSymbolAddress((void**)&wpTl, g_wphiTl);
    cudaGetSymbolAddress((void**)&wmBh, g_wmBh); cudaGetSymbolAddress((void**)&wmBl, g_wmBl);
    cudaGetSymbolAddress((void**)&spTh, g_sppTh); cudaGetSymbolAddress((void**)&spTl, g_sppTl);
    cudaGetSymbolAddress((void**)&kkh, g_kkh);   cudaGetSymbolAddress((void**)&kkl, g_kkl);
    cudaGetSymbolAddress((void**)&vTh, g_vTh);   cudaGetSymbolAddress((void**)&vTl, g_vTl);
    cudaGetSymbolAddress((void**)&PTh, g_PTh);   cudaGetSymbolAddress((void**)&PTl, g_PTl);

    // 0. pack weights, zero spp pad rows
    pack_kernel<<<(CC * CC + 255) / 256, 256>>>(wth, wg, wphi, wmask);

    // 1. transpose-convert y and x to bf16 hi/lo [N, C]
    tconv_kernel<<<dim3(NN / 32, CC / 32, BB), dim3(32, 8)>>>(y, yTh, yTl);
    tconv_kernel<<<dim3(NN / 32, CC / 32, BB), dim3(32, 8)>>>(x, xTh, xTl);

    // 2. tg[m,n] = sum_c W_tg[m,c] * y[c,n]     (M=512, N=4096, K=512)
    gemm_mma<0><<<dim3(NN / 128, CC / 128, BB), 256, GSMEM_BYTES>>>(
        wh, wl, 0LL, CC, yTh, yTl, (long long)NN * CC, CC,
        tg, (long long)CC * NN, NN, nullptr, 0LL, CC);

    // 3. SPP pyramid -> spp^T bf16 hi/lo [B, s, ch]
    spp_kernel<<<BB * CC, 256>>>();

    // 4. kk[s,c] = sum_ic sppT[s,ic(theta)] * wphiT[c,ic]   (M=128, N=512, K=256)
    gemm_mma<0><<<dim3(CC / 128, 1, BB), 256, GSMEM_BYTES>>>(
        spTh, spTl, (long long)SP * CC, CC, wpTh, wpTl, 0LL, ICN,
        kkf, (long long)SP * CC, CC, nullptr, 0LL, ICN);
    kkcvt_kernel<<<(BB * SP * CC + 255) / 256, 256>>>();

    // 5. v[s,c] = sum_ic sppT[s, 256+ic(g)] * wmask[c,ic]   (M=128, N=512, K=256)
    gemm_mma<0><<<dim3(CC / 128, 1, BB), 256, GSMEM_BYTES>>>(
        spTh + ICN, spTl + ICN, (long long)SP * CC, CC, wmBh, wmBl, 0LL, ICN,
        v, (long long)SP * CC, CC, nullptr, 0LL, ICN);

    // 6. logits[s,n] = sum_c kk[s,c] * x[c,n]   (M=128, N=4096, K=512)
    gemm_mma<0><<<dim3(NN / 128, 1, BB), 256, GSMEM_BYTES>>>(
        kkh, kkl, (long long)SP * CC, CC, xTh, xTl, (long long)NN * CC, CC,
        logits, (long long)SP * NN, NN, nullptr, 0LL, CC);

    // 7. per-(b,s) max + 1/sum(exp)
    rowstat_kernel<<<dim3(SS, BB), 256>>>();

    // 8. exp + transpose -> PT bf16 hi/lo [n, s]
    texp_kernel<<<dim3(NN / 32, BB), 256>>>();

    // 9. scale v by invsum, transpose -> vT bf16 hi/lo [c, s]
    vt_kernel<<<(BB * CC * SP + 255) / 256, 256>>>();

    // 10. out[c,n] = x[c,n] + sum_s vT[c,s] * PT[n,s]   (M=512, N=4096, K=128)
    gemm_mma<1><<<dim3(NN / 128, CC / 128, BB), 256, GSMEM_BYTES>>>(
        vTh, vTl, (long long)CC * SP, SP, PTh, PTl, (long long)NN * SP, SP,
        out, (long long)CC * NN, NN, x, (long long)CC * NN, SP);
}

// round 6
// speedup vs baseline: 2.3311x; 1.0045x over previous
#include <cuda_runtime.h>
#include <cuda_bf16.h>
#include <math.h>
#include <stdint.h>

// ---------------- problem constants ----------------
#define BB  16
#define CC  512
#define ICN 256
#define HH  64
#define NN  4096
#define SS  110
#define SP  128     // padded S

// ---------------- scratch (device globals) ----------------
__device__ float         g_tg[(long long)BB * CC * NN];        // theta/g conv out fp32 [B,512,N]
__device__ __nv_bfloat16 g_yTh[(long long)BB * NN * CC];       // y transposed bf16 hi [B,N,C]
__device__ __nv_bfloat16 g_yTl[(long long)BB * NN * CC];
__device__ __nv_bfloat16 g_xTh[(long long)BB * NN * CC];
__device__ __nv_bfloat16 g_xTl[(long long)BB * NN * CC];
__device__ __nv_bfloat16 g_wh[CC * CC];                        // [theta;g] weights [m,k]
__device__ __nv_bfloat16 g_wl[CC * CC];
__device__ __nv_bfloat16 g_wphiTh[CC * ICN];                   // w_phi^T [c, ic]
__device__ __nv_bfloat16 g_wphiTl[CC * ICN];
__device__ __nv_bfloat16 g_wmBh[CC * ICN];                     // w_mask [c, ic] (native)
__device__ __nv_bfloat16 g_wmBl[CC * ICN];
__device__ __nv_bfloat16 g_sppTh[BB * SP * CC];                // spp^T bf16 [B, s(pad), ch]
__device__ __nv_bfloat16 g_sppTl[BB * SP * CC];
__device__ float         g_kkf[BB * SP * CC];                  // kk fp32 [B, s, c]
__device__ __nv_bfloat16 g_kkh[BB * SP * CC];
__device__ __nv_bfloat16 g_kkl[BB * SP * CC];
__device__ float         g_v[BB * SP * CC];                    // v fp32 [B, s, c]
__device__ __nv_bfloat16 g_vTh[BB * CC * SP];                  // v^T bf16 [B, c, s]
__device__ __nv_bfloat16 g_vTl[BB * CC * SP];
__device__ float         g_logits[(long long)BB * SP * NN];    // [B, s(pad), n]
__device__ __nv_bfloat16 g_PTh[(long long)BB * NN * SP];       // exp(logits)^T [B, n, s]
__device__ __nv_bfloat16 g_PTl[(long long)BB * NN * SP];
__device__ float         g_max[BB * SS];
__device__ float         g_invsum[BB * SS];

// ---------------- helpers ----------------
__device__ __forceinline__ uint32_t smem_u32(const void* p) {
    uint32_t a;
    asm("{ .reg .u64 t; cvta.to.shared.u64 t, %1; cvt.u32.u64 %0, t; }" : "=r"(a) : "l"(p));
    return a;
}

#define CP_ASYNC16(saddr, gaddr) \
    asm volatile("cp.async.cg.shared.global [%0], [%1], 16;" :: "r"(saddr), "l"(gaddr))
#define CP_COMMIT() asm volatile("cp.async.commit_group;")
#define CP_WAIT0()  asm volatile("cp.async.wait_group 0;")

#define LDSM4(r0, r1, r2, r3, addr) \
    asm volatile("ldmatrix.sync.aligned.m8n8.x4.shared.b16 {%0,%1,%2,%3}, [%4];" \
                 : "=r"(r0), "=r"(r1), "=r"(r2), "=r"(r3) : "r"(addr))

#define MMA16816(d, a, b) \
    asm volatile("mma.sync.aligned.m16n8k16.row.col.f32.bf16.bf16.f32 " \
                 "{%0,%1,%2,%3}, {%4,%5,%6,%7}, {%8,%9}, {%0,%1,%2,%3};" \
                 : "+f"((d)[0]), "+f"((d)[1]), "+f"((d)[2]), "+f"((d)[3]) \
                 : "r"((a)[0]), "r"((a)[1]), "r"((a)[2]), "r"((a)[3]), \
                   "r"((b)[0]), "r"((b)[1]))

// ---------------- bf16x3 mma.sync GEMM ----------------
// C[m,n] = sum_k A[m,k]*B[n,k]  (both [rows, K] K-contiguous, bf16 hi/lo)
// BM=BN=128, BK=32, 8 warps (2x4, warp tile 64x32), padded smem rows (K32+8).
// 2-stage cp.async double buffer, ONE barrier per k-tile:
//   wait(load kt) -> sync -> issue load(kt+1) -> compute(kt)
// The sync proves all warps finished compute(kt-1), so load(kt+1) may safely
// overwrite that buffer; no trailing barrier needed. 2 CTAs/SM.
#define LDP       40                 // padded row length (elements)
#define TILE_B    (128 * LDP * 2)    // 10240 bytes per operand tile
#define STAGE_B   (4 * TILE_B)       // Ah, Al, Bh, Bl
#define GSMEM_BYTES (2 * STAGE_B)    // 81920

template <int ADD>
__global__ void __launch_bounds__(256, 2)
gemm_mma(const __nv_bfloat16* __restrict__ Ah, const __nv_bfloat16* __restrict__ Al,
         long long sA, int lda,
         const __nv_bfloat16* __restrict__ Bh, const __nv_bfloat16* __restrict__ Bl,
         long long sB, int ldb,
         float* __restrict__ C, long long sC, int ldc,
         const float* __restrict__ Cadd, long long sAdd, int K)
{
    extern __shared__ char smem_raw[];
    const uint32_t sb = smem_u32(smem_raw);
    const int tid = threadIdx.x, wid = tid >> 5, lane = tid & 31;
    const int wm = wid & 1, wn = wid >> 1;       // 2 x 4 warp grid
    const int b = blockIdx.z;
    const int bm = blockIdx.y * 128, bn = blockIdx.x * 128;
    Ah += b * sA; Al += b * sA; Bh += b * sB; Bl += b * sB;
    C += b * sC;
    if (ADD) Cadd += b * sAdd;

    const int nkt = K >> 5;

    // cp.async loader for one k-tile into stage buffer
    auto load_stage = [&](int kt, int buf) {
        const uint32_t stg = sb + buf * STAGE_B;
        const int k0 = kt << 5;
#pragma unroll
        for (int i = 0; i < 2; i++) {
            int id = tid + (i << 8);             // 0..511
            int row = id >> 2, cq = (id & 3) << 3;   // cq in elements (8 each)
            uint32_t soff = row * (LDP * 2) + (cq << 1);
            CP_ASYNC16(stg + 0 * TILE_B + soff, (const char*)(Ah + (long long)(bm + row) * lda + k0 + cq));
            CP_ASYNC16(stg + 1 * TILE_B + soff, (const char*)(Al + (long long)(bm + row) * lda + k0 + cq));
            CP_ASYNC16(stg + 2 * TILE_B + soff, (const char*)(Bh + (long long)(bn + row) * ldb + k0 + cq));
            CP_ASYNC16(stg + 3 * TILE_B + soff, (const char*)(Bl + (long long)(bn + row) * ldb + k0 + cq));
        }
    };

    float acc[4][4][4];
#pragma unroll
    for (int mi = 0; mi < 4; mi++)
#pragma unroll
        for (int ni = 0; ni < 4; ni++)
#pragma unroll
            for (int r = 0; r < 4; r++) acc[mi][ni][r] = 0.f;

    // per-lane ldmatrix byte offsets within an operand tile
    const uint32_t a_lb = (wm * 64 + (lane & 15)) * (LDP * 2) + ((lane >> 4) << 4);
    const uint32_t b_lb = (wn * 32 + (lane & 7) + ((lane >> 4) << 3)) * (LDP * 2)
                        + (((lane >> 3) & 1) << 4);

    load_stage(0, 0); CP_COMMIT();

    for (int kt = 0; kt < nkt; kt++) {
        const int buf = kt & 1;
        CP_WAIT0();                      // tile kt resident
        __syncthreads();                 // all warps done with compute(kt-1)
        if (kt + 1 < nkt) {              // prefetch overwrites buffer of kt-1
            load_stage(kt + 1, buf ^ 1); CP_COMMIT();
        }

        const uint32_t stg = sb + buf * STAGE_B;
#pragma unroll
        for (int k16 = 0; k16 < 2; k16++) {
            const uint32_t kb = k16 << 5;        // 16 elements = 32 bytes
            uint32_t bh[4][2], bl[4][2];
#pragma unroll
            for (int p = 0; p < 2; p++) {
                uint32_t bd = stg + 2 * TILE_B + b_lb + p * 16 * (LDP * 2) + kb;
                LDSM4(bh[2 * p][0], bh[2 * p][1], bh[2 * p + 1][0], bh[2 * p + 1][1], bd);
                LDSM4(bl[2 * p][0], bl[2 * p][1], bl[2 * p + 1][0], bl[2 * p + 1][1], bd + TILE_B);
            }
#pragma unroll
            for (int mi = 0; mi < 4; mi++) {
                uint32_t ah[4], al[4];
                uint32_t ad = stg + a_lb + mi * 16 * (LDP * 2) + kb;
                LDSM4(ah[0], ah[1], ah[2], ah[3], ad);
                LDSM4(al[0], al[1], al[2], al[3], ad + TILE_B);
#pragma unroll
                for (int ni = 0; ni < 4; ni++) {
                    MMA16816(acc[mi][ni], ah, bh[ni]);
                    MMA16816(acc[mi][ni], ah, bl[ni]);
                    MMA16816(acc[mi][ni], al, bh[ni]);
                }
            }
        }
    }

    // epilogue: fragment layout row = lane/4 (+8), col = 2*(lane%4)
#pragma unroll
    for (int mi = 0; mi < 4; mi++) {
#pragma unroll
        for (int ni = 0; ni < 4; ni++) {
            int r0 = bm + wm * 64 + mi * 16 + (lane >> 2);
            int col = bn + wn * 32 + ni * 8 + ((lane & 3) << 1);
            float2 v01 = make_float2(acc[mi][ni][0], acc[mi][ni][1]);
            float2 v23 = make_float2(acc[mi][ni][2], acc[mi][ni][3]);
            if (ADD) {
                float2 a0 = *reinterpret_cast<const float2*>(Cadd + (long long)r0 * ldc + col);
                float2 a1 = *reinterpret_cast<const float2*>(Cadd + (long long)(r0 + 8) * ldc + col);
                v01.x += a0.x; v01.y += a0.y;
                v23.x += a1.x; v23.y += a1.y;
            }
            *reinterpret_cast<float2*>(C + (long long)r0 * ldc + col) = v01;
            *reinterpret_cast<float2*>(C + (long long)(r0 + 8) * ldc + col) = v23;
        }
    }
}

// ---------------- weight pack + pad zero ----------------
__global__ void pack_kernel(const float* __restrict__ wth, const float* __restrict__ wg,
                            const float* __restrict__ wphi, const float* __restrict__ wmask) {
    int idx = blockIdx.x * 256 + threadIdx.x;
    if (idx < CC * CC) {
        int m = idx / CC, k = idx % CC;
        float w = (m < ICN) ? wth[m * CC + k] : wg[(m - ICN) * CC + k];
        __nv_bfloat16 h = __float2bfloat16(w);
        g_wh[idx] = h;
        g_wl[idx] = __float2bfloat16(w - __bfloat162float(h));
    }
    if (idx < CC * ICN) {
        int c = idx / ICN, ic = idx % ICN;
        float wp = wphi[ic * CC + c];
        __nv_bfloat16 h = __float2bfloat16(wp);
        g_wphiTh[idx] = h;
        g_wphiTl[idx] = __float2bfloat16(wp - __bfloat162float(h));
        float wm = wmask[idx];            // wmask is [c, ic] row-major already
        __nv_bfloat16 hm = __float2bfloat16(wm);
        g_wmBh[idx] = hm;
        g_wmBl[idx] = __float2bfloat16(wm - __bfloat162float(hm));
    }
    if (idx < BB * (SP - SS) * CC) {      // zero spp^T pad rows every launch
        int b = idx / ((SP - SS) * CC);
        int rem = idx % ((SP - SS) * CC);
        int s = SS + rem / CC, c = rem % CC;
        long long o = ((long long)(b * SP) + s) * CC + c;
        g_sppTh[o] = __float2bfloat16(0.f);
        g_sppTl[o] = __float2bfloat16(0.f);
    }
}

// ---------------- fp32 [C, N] -> bf16 hi/lo [N, C] (transpose-convert) ----
__global__ void tconv_kernel(const float* __restrict__ src,
                             __nv_bfloat16* __restrict__ dh, __nv_bfloat16* __restrict__ dl) {
    __shared__ float sm[32][33];
    int n0 = blockIdx.x * 32, c0 = blockIdx.y * 32, b = blockIdx.z;
    int tx = threadIdx.x, ty = threadIdx.y;
    src += (long long)b * CC * NN;
#pragma unroll
    for (int r = 0; r < 4; r++)
        sm[ty + 8 * r][tx] = src[(long long)(c0 + ty + 8 * r) * NN + n0 + tx];
    __syncthreads();
#pragma unroll
    for (int r = 0; r < 4; r++) {
        int n = n0 + ty + 8 * r, c = c0 + tx;
        float v = sm[tx][ty + 8 * r];
        __nv_bfloat16 h = __float2bfloat16(v);
        long long o = ((long long)b * NN + n) * CC + c;
        dh[o] = h;
        dl[o] = __float2bfloat16(v - __bfloat162float(h));
    }
}

// ---------------- SPP pyramid (1/3/6/8) -> bf16 hi/lo transposed ----------
__device__ __forceinline__ void spp_bounds(int s, int& r0, int& r1, int& c0, int& c1) {
    int o, i;
    if (s == 0)      { o = 1; i = 0; }
    else if (s < 10) { o = 3; i = s - 1; }
    else if (s < 46) { o = 6; i = s - 10; }
    else             { o = 8; i = s - 46; }
    int r = i / o, c = i % o;
    r0 = (r * HH) / o; r1 = ((r + 1) * HH + o - 1) / o;
    c0 = (c * HH) / o; c1 = ((c + 1) * HH + o - 1) / o;
}

__global__ void spp_kernel() {
    int bid = blockIdx.x;                       // b*512 + ch
    int b = bid / CC, ch = bid % CC;
    const float* src = g_tg + (long long)bid * NN;
    __shared__ float t[NN];
    __shared__ float red[256];
    int tid = threadIdx.x;
    float mx = -INFINITY;
    for (int i = tid; i < NN; i += 256) {
        float vv = src[i];
        t[i] = vv;
        mx = fmaxf(mx, vv);
    }
    red[tid] = mx;
    __syncthreads();
    for (int st = 128; st > 0; st >>= 1) {
        if (tid < st) red[tid] = fmaxf(red[tid], red[tid + st]);
        __syncthreads();
    }
    if (tid < SS) {
        float out;
        if (tid == 0) out = red[0];
        else {
            int r0, r1, c0, c1;
            spp_bounds(tid, r0, r1, c0, c1);
            out = -INFINITY;
            for (int r = r0; r < r1; r++)
                for (int c = c0; c < c1; c++)
                    out = fmaxf(out, t[r * HH + c]);
        }
        __nv_bfloat16 h = __float2bfloat16(out);
        long long o = ((long long)(b * SP) + tid) * CC + ch;
        g_sppTh[o] = h;
        g_sppTl[o] = __float2bfloat16(out - __bfloat162float(h));
    }
}

// ---------------- kk fp32 -> bf16 hi/lo ----------------
__global__ void kkcvt_kernel() {
    int gid = blockIdx.x * 256 + threadIdx.x;
    if (gid < BB * SP * CC) {
        float v = g_kkf[gid];
        __nv_bfloat16 h = __float2bfloat16(v);
        g_kkh[gid] = h;
        g_kkl[gid] = __float2bfloat16(v - __bfloat162float(h));
    }
}

// ---------------- row stats: max + 1/sum(exp) per (b,s) ----------------
__global__ void rowstat_kernel() {
    int s = blockIdx.x, b = blockIdx.y;
    const float* row = g_logits + ((long long)(b * SP + s)) * NN;
    __shared__ float t[NN];
    __shared__ float red[256];
    int tid = threadIdx.x;
    float mx = -INFINITY;
    for (int i = tid; i < NN; i += 256) {
        float v = row[i];
        t[i] = v;
        mx = fmaxf(mx, v);
    }
    red[tid] = mx;
    __syncthreads();
    for (int st = 128; st > 0; st >>= 1) {
        if (tid < st) red[tid] = fmaxf(red[tid], red[tid + st]);
        __syncthreads();
    }
    mx = red[0];
    __syncthreads();
    float sum = 0.f;
    for (int i = tid; i < NN; i += 256) sum += __expf(t[i] - mx);
    red[tid] = sum;
    __syncthreads();
    for (int st = 128; st > 0; st >>= 1) {
        if (tid < st) red[tid] += red[tid + st];
        __syncthreads();
    }
    if (tid == 0) {
        g_max[b * SS + s] = mx;
        g_invsum[b * SS + s] = 1.0f / red[0];
    }
}

// ---------------- exp + transpose: logits [s,n] -> PT bf16 [n,s] ----------
__global__ void texp_kernel() {
    __shared__ float sm[32][SP + 1];
    __shared__ float gmx[SP];
    int b = blockIdx.y, n0 = blockIdx.x * 32;
    int tid = threadIdx.x;
    if (tid < SS) gmx[tid] = g_max[b * SS + tid];
    __syncthreads();
    int tx = tid & 31, ty = tid >> 5;          // ty 0..7
#pragma unroll
    for (int r = 0; r < 16; r++) {
        int s = ty + (r << 3);
        float e = 0.f;
        if (s < SS)
            e = __expf(g_logits[((long long)(b * SP + s)) * NN + n0 + tx] - gmx[s]);
        sm[tx][s] = e;
    }
    __syncthreads();
#pragma unroll
    for (int w = 0; w < 16; w++) {
        int idx = tid + (w << 8);
        int nl = idx >> 7, s = idx & 127;
        float v = sm[nl][s];
        __nv_bfloat16 h = __float2bfloat16(v);
        long long o = ((long long)(b * NN) + n0 + nl) * SP + s;
        g_PTh[o] = h;
        g_PTl[o] = __float2bfloat16(v - __bfloat162float(h));
    }
}

// ---------------- v [s,c] * invsum -> vT bf16 hi/lo [c,s] ----------------
__global__ void vt_kernel() {
    int gid = blockIdx.x * 256 + threadIdx.x;
    if (gid >= BB * CC * SP) return;
    int b = gid >> 16;                // CC*SP = 65536
    int rem = gid & 65535;
    int c = rem >> 7, s = rem & 127;
    float val = 0.f;
    if (s < SS)
        val = g_v[((long long)(b * SP + s)) * CC + c] * g_invsum[b * SS + s];
    __nv_bfloat16 h = __float2bfloat16(val);
    long long o = ((long long)b * CC + c) * SP + s;
    g_vTh[o] = h;
    g_vTl[o] = __float2bfloat16(val - __bfloat162float(h));
}

// ---------------- launch ----------------
extern "C" void kernel_launch(void* const* d_in, const int* in_sizes, int n_in,
                              void* d_out, int out_size) {
    const float* x     = (const float*)d_in[0];
    const float* y     = (const float*)d_in[1];
    const float* wphi  = (const float*)d_in[2];
    const float* wth   = (const float*)d_in[3];
    const float* wg    = (const float*)d_in[4];
    const float* wmask = (const float*)d_in[5];
    float* out = (float*)d_out;

    cudaFuncSetAttribute(gemm_mma<0>, cudaFuncAttributeMaxDynamicSharedMemorySize, GSMEM_BYTES);
    cudaFuncSetAttribute(gemm_mma<1>, cudaFuncAttributeMaxDynamicSharedMemorySize, GSMEM_BYTES);

    float *tg, *kkf, *v, *logits;
    __nv_bfloat16 *yTh, *yTl, *xTh, *xTl, *wh, *wl, *wpTh, *wpTl, *wmBh, *wmBl;
    __nv_bfloat16 *spTh, *spTl, *kkh, *kkl, *vTh, *vTl, *PTh, *PTl;
    cudaGetSymbolAddress((void**)&tg, g_tg);
    cudaGetSymbolAddress((void**)&kkf, g_kkf);
    cudaGetSymbolAddress((void**)&v, g_v);
    cudaGetSymbolAddress((void**)&logits, g_logits);
    cudaGetSymbolAddress((void**)&yTh, g_yTh);   cudaGetSymbolAddress((void**)&yTl, g_yTl);
    cudaGetSymbolAddress((void**)&xTh, g_xTh);   cudaGetSymbolAddress((void**)&xTl, g_xTl);
    cudaGetSymbolAddress((void**)&wh, g_wh);     cudaGetSymbolAddress((void**)&wl, g_wl);
    cudaGetSymbolAddress((void**)&wpTh, g_wphiTh); cudaGetSymbolAddress((void**)&wpTl, g_wphiTl);
    cudaGetSymbolAddress((void**)&wmBh, g_wmBh); cudaGetSymbolAddress((void**)&wmBl, g_wmBl);
    cudaGetSymbolAddress((void**)&spTh, g_sppTh); cudaGetSymbolAddress((void**)&spTl, g_sppTl);
    cudaGetSymbolAddress((void**)&kkh, g_kkh);   cudaGetSymbolAddress((void**)&kkl, g_kkl);
    cudaGetSymbolAddress((void**)&vTh, g_vTh);   cudaGetSymbolAddress((void**)&vTl, g_vTl);
    cudaGetSymbolAddress((void**)&PTh, g_PTh);   cudaGetSymbolAddress((void**)&PTl, g_PTl);

    // 0. pack weights, zero spp pad rows
    pack_kernel<<<(CC * CC + 255) / 256, 256>>>(wth, wg, wphi, wmask);

    // 1. transpose-convert y and x to bf16 hi/lo [N, C]
    tconv_kernel<<<dim3(NN / 32, CC / 32, BB), dim3(32, 8)>>>(y, yTh, yTl);
    tconv_kernel<<<dim3(NN / 32, CC / 32, BB), dim3(32, 8)>>>(x, xTh, xTl);

    // 2. tg[m,n] = sum_c W_tg[m,c] * y[c,n]     (M=512, N=4096, K=512)
    gemm_mma<0><<<dim3(NN / 128, CC / 128, BB), 256, GSMEM_BYTES>>>(
        wh, wl, 0LL, CC, yTh, yTl, (long long)NN * CC, CC,
        tg, (long long)CC * NN, NN, nullptr, 0LL, CC);

    // 3. SPP pyramid -> spp^T bf16 hi/lo [B, s, ch]
    spp_kernel<<<BB * CC, 256>>>();

    // 4. kk[s,c] = sum_ic sppT[s,ic(theta)] * wphiT[c,ic]   (M=128, N=512, K=256)
    gemm_mma<0><<<dim3(CC / 128, 1, BB), 256, GSMEM_BYTES>>>(
        spTh, spTl, (long long)SP * CC, CC, wpTh, wpTl, 0LL, ICN,
        kkf, (long long)SP * CC, CC, nullptr, 0LL, ICN);
    kkcvt_kernel<<<(BB * SP * CC + 255) / 256, 256>>>();

    // 5. v[s,c] = sum_ic sppT[s, 256+ic(g)] * wmask[c,ic]   (M=128, N=512, K=256)
    gemm_mma<0><<<dim3(CC / 128, 1, BB), 256, GSMEM_BYTES>>>(
        spTh + ICN, spTl + ICN, (long long)SP * CC, CC, wmBh, wmBl, 0LL, ICN,
        v, (long long)SP * CC, CC, nullptr, 0LL, ICN);

    // 6. logits[s,n] = sum_c kk[s,c] * x[c,n]   (M=128, N=4096, K=512)
    gemm_mma<0><<<dim3(NN / 128, 1, BB), 256, GSMEM_BYTES>>>(
        kkh, kkl, (long long)SP * CC, CC, xTh, xTl, (long long)NN * CC, CC,
        logits, (long long)SP * NN, NN, nullptr, 0LL, CC);

    // 7. per-(b,s) max + 1/sum(exp)
    rowstat_kernel<<<dim3(SS, BB), 256>>>();

    // 8. exp + transpose -> PT bf16 hi/lo [n, s]
    texp_kernel<<<dim3(NN / 32, BB), 256>>>();

    // 9. scale v by invsum, transpose -> vT bf16 hi/lo [c, s]
    vt_kernel<<<(BB * CC * SP + 255) / 256, 256>>>();

    // 10. out[c,n] = x[c,n] + sum_s vT[c,s] * PT[n,s]   (M=512, N=4096, K=128)
    gemm_mma<1><<<dim3(NN / 128, CC / 128, BB), 256, GSMEM_BYTES>>>(
        vTh, vTl, (long long)CC * SP, SP, PTh, PTl, (long long)NN * SP, SP,
        out, (long long)CC * NN, NN, x, (long long)CC * NN, SP);
}